// round 13
// baseline (speedup 1.0000x reference)
#include <cuda_runtime.h>
#include <mma.h>
#include <math.h>
#include <stdint.h>

#define NROWS 8192
#define DIM 512

__device__ float g_Q [NROWS*DIM];
__device__ float g_K [NROWS*DIM];
__device__ float g_V [NROWS*DIM];
__device__ float g_P0[NROWS*DIM];
__device__ float g_P1[NROWS*DIM];
__device__ float g_H [NROWS*DIM];

__device__ __forceinline__ float tf32r(float v) { return nvcuda::wmma::__float_to_tf32(v); }

__device__ __forceinline__ void mma8(float* c, const float* a, const float* b) {
    asm volatile("mma.sync.aligned.m16n8k8.row.col.f32.tf32.tf32.f32 "
        "{%0,%1,%2,%3}, {%4,%5,%6,%7}, {%8,%9}, {%0,%1,%2,%3};"
        : "+f"(c[0]), "+f"(c[1]), "+f"(c[2]), "+f"(c[3])
        : "r"(__float_as_uint(a[0])), "r"(__float_as_uint(a[1])),
          "r"(__float_as_uint(a[2])), "r"(__float_as_uint(a[3])),
          "r"(__float_as_uint(b[0])), "r"(__float_as_uint(b[1])));
}

__device__ __forceinline__ void cpa16(uint32_t dst, const void* src) {
    asm volatile("cp.async.cg.shared.global [%0], [%1], 16;" :: "r"(dst), "l"(src));
}
#define CPA_COMMIT() asm volatile("cp.async.commit_group;" ::: "memory")
#define CPA_WAIT0()  asm volatile("cp.async.wait_group 0;"  ::: "memory")
#define CPA_WAIT1()  asm volatile("cp.async.wait_group 1;"  ::: "memory")
#define CPA_WAIT2()  asm volatile("cp.async.wait_group 2;"  ::: "memory")

// ===========================================================================
// Retention partial: P = (D .* (Q K^T)) @ V over a 4096-wide j-range.
// CTA = 32 Q-rows, 256 thr (8 warps), 2 CTAs/SM (launch_bounds(256,2)).
// grid 512 = 256 qblocks x 2 jsplits.  j-chunk 128.
//   QK: S 32x128, warp grid 1x8, warp tile 32x16. 32-col K stages, 3-slot
//       ring; D tile folded into stage cp.async groups (2 rows/stage).
//   D-phase: Ssp = tf32(S .* D), pair-interleaved (stride 136).
//   SV: O 32x512, warp grid 1x8, warp tile 32x64. 8-row V stages, 4-slot
//       ring (slots 0-2 in post-QK ring tail, slot 3 overlays dead Ds).
// SMEM (floats): ring 3*6400=19200 (after QK: Ssp[32*136]=4352 + vslot0..2)
//   + Ds[32][132]=4224 (vslot3 after D-phase).  23424 fl = 93696 B.
// Q,K arrive pair-interleaved within 8-col groups (producer PERM).
// ===========================================================================
#define STG_FL   6400               // Q 32x40 + K 128x40
#define RING_FL  19200
#define DS_FL    4224
#define VSLOT_FL 4160               // 8 rows x 520
#define SSP_FL   4352               // 32 x 136
#define RET_SMEM ((RING_FL + DS_FL) * 4)   // 93696

__device__ __forceinline__ uint32_t vslot_off(int i) {
    // slots 0..2 at 4352 + i*4160 ; slot 3 at 19200 (Ds region)
    return 4352u + (uint32_t)i * 4160u + (uint32_t)((i + 1) >> 2) * 2368u;
}

__global__ void __launch_bounds__(256, 2) retention_mma(
    const float* __restrict__ Q, const float* __restrict__ K,
    const float* __restrict__ V, const float* __restrict__ D,
    float* __restrict__ P0, float* __restrict__ P1)
{
    extern __shared__ float sm[];
    float* ring = sm;
    float* Ssp  = sm;                                  // 32 x 136 after QK
    float (*Ds)[132] = (float(*)[132])(sm + RING_FL);

    const int tid = threadIdx.x;
    const int lane = tid & 31, wn = tid >> 5;          // 8 warps, 1x8 grid
    const int qr = lane >> 2, qc = lane & 3;
    const int qb = blockIdx.x >> 1, js = blockIdx.x & 1;
    const int i0 = qb * 32;
    const int jb0 = js * 4096;
    float* Pout = js ? P1 : P0;

    const uint32_t sBase = (uint32_t)__cvta_generic_to_shared(sm);
    const uint32_t sDs   = sBase + RING_FL * 4u;

    // loader indices
    const int lq_r = tid >> 3,  lq_c = (tid & 7) * 4;     // Q: 32 rows, 1 ld
    const int lk_r = tid >> 3,  lk_c = (tid & 7) * 4;     // K: 4 x 32 rows
    const int lv_r = tid >> 7,  lv_c = (tid & 127) * 4;   // V: 4 passes, 2 rows
    const int ld_r = tid >> 5,  ld_c = (tid & 31) * 4;    // D: tid<64, 2 rows

    const int spos = ((2*qc) & 3) * 2 + (qc >> 1);        // paired pos base

    float o[2][8][4];
    #pragma unroll
    for (int f = 0; f < 2; f++)
        #pragma unroll
        for (int g = 0; g < 8; g++)
            #pragma unroll
            for (int e = 0; e < 4; e++) o[f][g][e] = 0.f;

    #pragma unroll 1
    for (int j0 = jb0; j0 < jb0 + 4096; j0 += 128) {
        // ---- QK stage issue (stage kc -> ring slot kc%3; carries 2 D rows) --
        auto issue_qk = [&](int kc) {
            uint32_t b = sBase + (uint32_t)((kc % 3) * STG_FL) * 4u;
            cpa16(b + (uint32_t)(lq_r*40 + lq_c)*4u,
                  &Q[(size_t)(i0 + lq_r)*DIM + kc*32 + lq_c]);
            #pragma unroll
            for (int p = 0; p < 4; p++) {
                int r = lk_r + p*32;
                cpa16(b + (uint32_t)(1280 + r*40 + lk_c)*4u,
                      &K[(size_t)(j0 + r)*DIM + kc*32 + lk_c]);
            }
            if (tid < 64) {
                int dr = kc*2 + ld_r;
                cpa16(sDs + (uint32_t)(dr*132 + ld_c)*4u,
                      &D[(size_t)(i0 + dr)*NROWS + j0 + ld_c]);
            }
            CPA_COMMIT();
        };

        issue_qk(0);
        issue_qk(1);

        float s[2][2][4];
        #pragma unroll
        for (int f = 0; f < 2; f++)
            #pragma unroll
            for (int g = 0; g < 2; g++)
                #pragma unroll
                for (int e = 0; e < 4; e++) s[f][g][e] = 0.f;

        // ---------------- QK:  S = Q @ K[j0:j0+128]^T ----------------
        #pragma unroll 1
        for (int kc = 0; kc < 16; kc++) {
            if (kc < 15) { CPA_WAIT1(); } else { CPA_WAIT0(); }
            __syncthreads();
            if (kc < 14) issue_qk(kc + 2);
            const float* Qs = ring + (kc % 3) * STG_FL;
            const float* Ks = Qs + 1280;
            #pragma unroll
            for (int k8 = 0; k8 < 4; k8++) {
                const int kp = k8*8 + 2*qc;     // paired (k, k+4)
                float a[2][4];
                #pragma unroll
                for (int f = 0; f < 2; f++) {
                    int rb = f*16 + qr;
                    float2 a0 = *(const float2*)&Qs[rb*40 + kp];
                    float2 a1 = *(const float2*)&Qs[(rb+8)*40 + kp];
                    a[f][0] = a0.x; a[f][1] = a1.x; a[f][2] = a0.y; a[f][3] = a1.y;
                }
                #pragma unroll
                for (int g = 0; g < 2; g++) {
                    int nb = wn*16 + g*8 + qr;
                    float2 bb = *(const float2*)&Ks[nb*40 + kp];
                    float b[2] = { bb.x, bb.y };
                    mma8(s[0][g], a[0], b);
                    mma8(s[1][g], a[1], b);
                }
            }
        }
        __syncthreads();   // QK reads done -> Ssp / vslot0..2 (alias ring)

        // ---- SV stage issue (stage st -> vslot st%4, 8 V-rows) ----
        auto issue_v = [&](int st) {
            uint32_t b = sBase + vslot_off(st & 3) * 4u;
            #pragma unroll
            for (int p = 0; p < 4; p++) {
                int r = lv_r + p*2;
                cpa16(b + (uint32_t)(r*520 + lv_c)*4u,
                      &V[(size_t)(j0 + st*8 + r)*DIM + lv_c]);
            }
            CPA_COMMIT();
        };

        issue_v(0);
        issue_v(1);

        // ------- D-phase: Ssp = tf32(S .* Ds), pair-interleaved writes -------
        #pragma unroll
        for (int f = 0; f < 2; f++)
            #pragma unroll
            for (int g = 0; g < 2; g++) {
                int r = f*16 + qr;
                int c = wn*16 + g*8 + 2*qc;
                int G8 = (wn*2 + g)*8;
                float2 d0 = *(float2*)&Ds[r][c];
                float2 d1 = *(float2*)&Ds[r+8][c];
                Ssp[r*136 + G8 + spos]         = tf32r(s[f][g][0]*d0.x);
                Ssp[r*136 + G8 + spos + 2]     = tf32r(s[f][g][1]*d0.y);
                Ssp[(r+8)*136 + G8 + spos]     = tf32r(s[f][g][2]*d1.x);
                Ssp[(r+8)*136 + G8 + spos + 2] = tf32r(s[f][g][3]*d1.y);
            }
        __syncthreads();   // Ds reads done -> vslot3 (aliases Ds) usable

        issue_v(2);

        // ------------- SV:  O += Ssp @ V[j0:j0+128]  (16 stages) -------------
        #pragma unroll 1
        for (int st = 0; st < 16; st++) {
            if (st < 14) { CPA_WAIT2(); }
            else if (st < 15) { CPA_WAIT1(); }
            else { CPA_WAIT0(); }
            __syncthreads();
            if (st + 3 < 16) issue_v(st + 3);
            const float* Vb = sm + vslot_off(st & 3);
            const int G8 = st*8;
            float a[2][4];
            #pragma unroll
            for (int f = 0; f < 2; f++) {
                int rb = f*16 + qr;
                float2 p0 = *(const float2*)&Ssp[rb*136 + G8 + 2*qc];
                float2 p1 = *(const float2*)&Ssp[(rb+8)*136 + G8 + 2*qc];
                a[f][0] = p0.x; a[f][1] = p1.x; a[f][2] = p0.y; a[f][3] = p1.y;
            }
            const float* v0 = Vb + qc*520;
            const float* v1 = Vb + (qc+4)*520;
            #pragma unroll
            for (int g = 0; g < 8; g++) {
                int n = wn*64 + g*8 + qr;
                float b[2] = { v0[n], v1[n] };
                mma8(o[0][g], a[0], b);
                mma8(o[1][g], a[1], b);
            }
        }
        __syncthreads();   // all Ssp/V reads done before next chunk's issues
    }

    // ---------------- epilogue ----------------
    #pragma unroll
    for (int f = 0; f < 2; f++)
        #pragma unroll
        for (int g = 0; g < 8; g++) {
            int r = i0 + f*16 + qr;
            int c = wn*64 + g*8 + 2*qc;
            *(float2*)&Pout[(size_t)r*DIM + c]       = make_float2(o[f][g][0], o[f][g][1]);
            *(float2*)&Pout[(size_t)(r + 8)*DIM + c] = make_float2(o[f][g][2], o[f][g][3]);
        }
}

// ===========================================================================
// Small GEMMs, single-pass tf32: C = act((A [+A2]) @ B + bias).
// BM=128, BN=64, BK=32.  256 thr, warps 4(m) x 2(n), warp tile 32x32.
// PERM=1: pair-interleave output columns within each 8-group (Q, K).
// ===========================================================================
#define GEMM_SMEM 27648

template<int ACT, int ROUND, int PERM, int ADD>
__global__ void __launch_bounds__(256) gemm_tf32(
    const float* __restrict__ A, const float* __restrict__ A2,
    const float* __restrict__ B,
    const float* __restrict__ bias, float* __restrict__ C)
{
    extern __shared__ float sm[];
    float (*As)[36] = (float(*)[36]) sm;
    float (*Bs)[72] = (float(*)[72])(sm + 4608);

    const int tid = threadIdx.x;
    const int lane = tid & 31, w = tid >> 5;
    const int wm = w >> 1, wn = w & 1;
    const int qr = lane >> 2, qc = lane & 3;
    const int bm = blockIdx.x * 128, bn = blockIdx.y * 64;

    float acc[2][4][4];
    #pragma unroll
    for (int f = 0; f < 2; f++)
        #pragma unroll
        for (int g = 0; g < 4; g++)
            #pragma unroll
            for (int e = 0; e < 4; e++) acc[f][g][e] = 0.f;

    float4 ap[4]; float4 bp[2];
    #pragma unroll
    for (int p = 0; p < 4; p++) {
        int idx = tid + p*256, r = idx >> 3, c4 = (idx & 7) * 4;
        ap[p] = *(const float4*)&A[(size_t)(bm + r)*DIM + c4];
        if (ADD) {
            float4 t = *(const float4*)&A2[(size_t)(bm + r)*DIM + c4];
            ap[p].x += t.x; ap[p].y += t.y; ap[p].z += t.z; ap[p].w += t.w;
        }
    }
    #pragma unroll
    for (int p = 0; p < 2; p++) {
        int idx = tid + p*256, r = idx >> 4, c4 = (idx & 15) * 4;
        bp[p] = *(const float4*)&B[(size_t)r*DIM + bn + c4];
    }

    #pragma unroll 1
    for (int kc = 0; kc < 16; kc++) {
        #pragma unroll
        for (int p = 0; p < 4; p++) {
            int idx = tid + p*256, r = idx >> 3, c4 = (idx & 7) * 4;
            As[r][c4+0] = tf32r(ap[p].x); As[r][c4+1] = tf32r(ap[p].y);
            As[r][c4+2] = tf32r(ap[p].z); As[r][c4+3] = tf32r(ap[p].w);
        }
        #pragma unroll
        for (int p = 0; p < 2; p++) {
            int idx = tid + p*256, r = idx >> 4, c4 = (idx & 15) * 4;
            Bs[r][c4+0] = tf32r(bp[p].x); Bs[r][c4+1] = tf32r(bp[p].y);
            Bs[r][c4+2] = tf32r(bp[p].z); Bs[r][c4+3] = tf32r(bp[p].w);
        }
        __syncthreads();
        if (kc < 15) {
            #pragma unroll
            for (int p = 0; p < 4; p++) {
                int idx = tid + p*256, r = idx >> 3, c4 = (idx & 7) * 4;
                ap[p] = *(const float4*)&A[(size_t)(bm + r)*DIM + (kc+1)*32 + c4];
                if (ADD) {
                    float4 t = *(const float4*)&A2[(size_t)(bm + r)*DIM + (kc+1)*32 + c4];
                    ap[p].x += t.x; ap[p].y += t.y; ap[p].z += t.z; ap[p].w += t.w;
                }
            }
            #pragma unroll
            for (int p = 0; p < 2; p++) {
                int idx = tid + p*256, r = idx >> 4, c4 = (idx & 15) * 4;
                bp[p] = *(const float4*)&B[(size_t)((kc+1)*32 + r)*DIM + bn + c4];
            }
        }
        #pragma unroll
        for (int k8 = 0; k8 < 4; k8++) {
            const int kk = k8*8 + qc;
            float a[2][4];
            #pragma unroll
            for (int f = 0; f < 2; f++) {
                int rb = wm*32 + f*16 + qr;
                a[f][0] = As[rb][kk];   a[f][1] = As[rb+8][kk];
                a[f][2] = As[rb][kk+4]; a[f][3] = As[rb+8][kk+4];
            }
            #pragma unroll
            for (int g = 0; g < 4; g++) {
                int n = wn*32 + g*8 + qr;
                float b[2] = { Bs[kk][n], Bs[kk+4][n] };
                mma8(acc[0][g], a[0], b);
                mma8(acc[1][g], a[1], b);
            }
        }
        __syncthreads();
    }

    #pragma unroll
    for (int f = 0; f < 2; f++)
        #pragma unroll
        for (int g = 0; g < 4; g++) {
            int r = bm + wm*32 + f*16 + qr;
            int c = bn + wn*32 + g*8 + 2*qc;
            float2 bb = *(const float2*)&bias[c];
            float v0 = acc[f][g][0] + bb.x, v1 = acc[f][g][1] + bb.y;
            float v2 = acc[f][g][2] + bb.x, v3 = acc[f][g][3] + bb.y;
            if (ACT == 1) {
                v0 = 0.5f*v0*(1.f + erff(v0*0.70710678118654752f));
                v1 = 0.5f*v1*(1.f + erff(v1*0.70710678118654752f));
                v2 = 0.5f*v2*(1.f + erff(v2*0.70710678118654752f));
                v3 = 0.5f*v3*(1.f + erff(v3*0.70710678118654752f));
            }
            if (ROUND == 1) { v0 = tf32r(v0); v1 = tf32r(v1); v2 = tf32r(v2); v3 = tf32r(v3); }
            if (PERM == 1) {
                int m0 = c & 7;            // even cols: 0,2,4,6
                int m1 = (c + 1) & 7;      // odd cols:  1,3,5,7
                int p0 = (c & ~7) + ((m0 < 4) ? 2*m0 : 2*(m0-4)+1);
                int p1 = (c & ~7) + ((m1 < 4) ? 2*m1 : 2*(m1-4)+1);
                C[(size_t)r*DIM + p0]       = v0;
                C[(size_t)r*DIM + p1]       = v1;
                C[(size_t)(r + 8)*DIM + p0] = v2;
                C[(size_t)(r + 8)*DIM + p1] = v3;
            } else {
                *(float2*)&C[(size_t)r*DIM + c]       = make_float2(v0, v1);
                *(float2*)&C[(size_t)(r + 8)*DIM + c] = make_float2(v2, v3);
            }
        }
}

// ---------------------------------------------------------------------------
__global__ void groupnorm_kernel(float* __restrict__ out,
                                 const float* __restrict__ gamma,
                                 const float* __restrict__ beta)
{
    __shared__ float buf[512];
    __shared__ float smu[16], siv[16];
    const int row = blockIdx.x;
    const int tid = threadIdx.x;
    float* p = out + (size_t)row * DIM;
    buf[tid]       = p[tid];
    buf[tid + 256] = p[tid + 256];
    __syncthreads();
    if (tid < 16) {
        float sx = 0.f, s2 = 0.f;
        #pragma unroll
        for (int c = 0; c < 32; c++) { float v = buf[tid*32 + c]; sx += v; s2 += v*v; }
        float mu  = sx * (1.f/32.f);
        float var = s2 * (1.f/32.f) - mu*mu;
        smu[tid] = mu;
        siv[tid] = rsqrtf(var + 1e-5f);
    }
    __syncthreads();
    #pragma unroll
    for (int q = 0; q < 2; q++) {
        int c = tid + q*256;
        int g = c >> 5;
        p[c] = (buf[c] - smu[g]) * siv[g] * gamma[c] + beta[c];
    }
}

// ---------------------------------------------------------------------------
extern "C" void kernel_launch(void* const* d_in, const int* in_sizes, int n_in,
                              void* d_out, int out_size)
{
    const float* x     = (const float*)d_in[0];
    const float* D     = (const float*)d_in[1];
    const float* Wq    = (const float*)d_in[2];
    const float* bq    = (const float*)d_in[3];
    const float* Wk    = (const float*)d_in[4];
    const float* bk    = (const float*)d_in[5];
    const float* Wv    = (const float*)d_in[6];
    const float* bv    = (const float*)d_in[7];
    const float* Wf    = (const float*)d_in[8];
    const float* bf    = (const float*)d_in[9];
    const float* Wp    = (const float*)d_in[10];
    const float* bp    = (const float*)d_in[11];
    const float* gamma = (const float*)d_in[12];
    const float* beta  = (const float*)d_in[13];
    float* out = (float*)d_out;

    float *Q, *K, *V, *P0, *P1, *H;
    cudaGetSymbolAddress((void**)&Q,  g_Q);
    cudaGetSymbolAddress((void**)&K,  g_K);
    cudaGetSymbolAddress((void**)&V,  g_V);
    cudaGetSymbolAddress((void**)&P0, g_P0);
    cudaGetSymbolAddress((void**)&P1, g_P1);
    cudaGetSymbolAddress((void**)&H,  g_H);

    cudaFuncSetAttribute(gemm_tf32<0,1,1,0>,
                         cudaFuncAttributeMaxDynamicSharedMemorySize, GEMM_SMEM);
    cudaFuncSetAttribute(gemm_tf32<0,1,0,0>,
                         cudaFuncAttributeMaxDynamicSharedMemorySize, GEMM_SMEM);
    cudaFuncSetAttribute(gemm_tf32<1,0,0,1>,
                         cudaFuncAttributeMaxDynamicSharedMemorySize, GEMM_SMEM);
    cudaFuncSetAttribute(gemm_tf32<0,0,0,0>,
                         cudaFuncAttributeMaxDynamicSharedMemorySize, GEMM_SMEM);
    cudaFuncSetAttribute(retention_mma,
                         cudaFuncAttributeMaxDynamicSharedMemorySize, RET_SMEM);

    dim3 gs(NROWS/128, DIM/64);    // 64 x 8
    gemm_tf32<0,1,1,0><<<gs, 256, GEMM_SMEM>>>(x, x, Wq, bq, Q);   // Q: permuted
    gemm_tf32<0,1,1,0><<<gs, 256, GEMM_SMEM>>>(x, x, Wk, bk, K);   // K: permuted
    gemm_tf32<0,1,0,0><<<gs, 256, GEMM_SMEM>>>(x, x, Wv, bv, V);   // V: normal

    retention_mma<<<512, 256, RET_SMEM>>>(Q, K, V, D, P0, P1);

    gemm_tf32<1,0,0,1><<<gs, 256, GEMM_SMEM>>>(P0, P1, Wf, bf, H); // GELU + P0+P1
    gemm_tf32<0,0,0,0><<<gs, 256, GEMM_SMEM>>>(H, H, Wp, bp, out);

    groupnorm_kernel<<<NROWS, 256>>>(out, gamma, beta);
}

// round 14
// speedup vs baseline: 1.2459x; 1.2459x over previous
#include <cuda_runtime.h>
#include <mma.h>
#include <math.h>
#include <stdint.h>

#define NROWS 8192
#define DIM 512

__device__ float g_Q [NROWS*DIM];
__device__ float g_K [NROWS*DIM];
__device__ float g_V [NROWS*DIM];
__device__ float g_XR[NROWS*DIM];
__device__ float g_H [NROWS*DIM];

__device__ __forceinline__ float tf32r(float v) { return nvcuda::wmma::__float_to_tf32(v); }

__device__ __forceinline__ void mma8(float* c, const float* a, const float* b) {
    asm volatile("mma.sync.aligned.m16n8k8.row.col.f32.tf32.tf32.f32 "
        "{%0,%1,%2,%3}, {%4,%5,%6,%7}, {%8,%9}, {%0,%1,%2,%3};"
        : "+f"(c[0]), "+f"(c[1]), "+f"(c[2]), "+f"(c[3])
        : "r"(__float_as_uint(a[0])), "r"(__float_as_uint(a[1])),
          "r"(__float_as_uint(a[2])), "r"(__float_as_uint(a[3])),
          "r"(__float_as_uint(b[0])), "r"(__float_as_uint(b[1])));
}

__device__ __forceinline__ void cpa16(uint32_t dst, const void* src) {
    asm volatile("cp.async.cg.shared.global [%0], [%1], 16;" :: "r"(dst), "l"(src));
}
#define CPA_COMMIT() asm volatile("cp.async.commit_group;" ::: "memory")
#define CPA_WAIT0()  asm volatile("cp.async.wait_group 0;"  ::: "memory")
#define CPA_WAIT1()  asm volatile("cp.async.wait_group 1;"  ::: "memory")
#define CPA_WAIT2()  asm volatile("cp.async.wait_group 2;"  ::: "memory")

// ===========================================================================
// Retention: O = (D .* (Q K^T)) @ V.  CTA = 64 Q-rows, 512 thr (16 warps).
// j-chunk 256.  Q,K pair-interleaved within 8-col groups (producer PERM=1).
// V stored as V'': element (j,n) at (j>>3)*4096 + n*8 + pp(j&7), so SV
// B-fragments (V[k][n], V[k+4][n]) are adjacent -> LDS.64; V stages are
// LINEAR cp.async copies (16 rows = 8192 fl, no padding).
//   QK: S 64x256, warp grid 2x8, tile 32x32, 32-col stages, 3-slot ring,
//       D tile folded into stage cp.async groups.
//   D-phase: Ssp = tf32(S .* D), pair-interleaved (stride 264).
//   SV: O 64x512, warp grid 2x8, tile 32x64, 16-row V stages, 4-slot ring
//       (slots 0,1 in post-QK ring tail, slots 2,3 overlay Ds region).
// SMEM: ring 3*12800=38400 fl (after QK: Ssp 16896 + vslot0 16896..25087 +
//       vslot1 25088..33279) + region2 16640 fl (Ds / vslot2,3).
//       55040 fl = 220160 B.
// ===========================================================================
#define STG_FL   12800
#define RING_FL  38400
#define REG2_FL  16640
#define SSP_FL   16896              // 64 x 264
#define RET_SMEM ((RING_FL + REG2_FL) * 4)

__global__ void __launch_bounds__(512, 1) retention_mma(
    const float* __restrict__ Q, const float* __restrict__ K,
    const float* __restrict__ V, const float* __restrict__ D,
    float* __restrict__ O)
{
    extern __shared__ float sm[];
    float* ring = sm;
    float* Ssp  = sm;                                  // paired S, 64 x 264
    float (*Ds)[260] = (float(*)[260])(sm + RING_FL);

    const int vofs[4] = { SSP_FL, SSP_FL + 8192, RING_FL, RING_FL + 8192 };

    const int tid = threadIdx.x;
    const int lane = tid & 31, w = tid >> 5;
    const int wm = w >> 3, wn = w & 7;       // 2 x 8 warp grid
    const int qr = lane >> 2, qc = lane & 3;
    const int i0 = blockIdx.x * 64;

    const uint32_t sBase = (uint32_t)__cvta_generic_to_shared(sm);
    const uint32_t sDs   = sBase + RING_FL * 4u;

    // loader indices
    const int lq_r = tid >> 3,  lq_c = (tid & 7) * 4;     // Q: 64 rows
    const int lk_r = tid >> 3,  lk_c = (tid & 7) * 4;     // K: 4 x 64 rows
    const int ld_r = tid >> 6,  ld_c = (tid & 63) * 4;    // D (tid<256)

    const int spos = ((2*qc) & 3) * 2 + (qc >> 1);        // Ssp paired pos base

    float o[2][8][4];
    #pragma unroll
    for (int f = 0; f < 2; f++)
        #pragma unroll
        for (int g = 0; g < 8; g++)
            #pragma unroll
            for (int e = 0; e < 4; e++) o[f][g][e] = 0.f;

    #pragma unroll 1
    for (int j0 = 0; j0 < NROWS; j0 += 256) {
        // ---- QK stage issue (stage kc -> ring slot kc%3; carries D rows) ----
        auto issue_qk = [&](int kc) {
            uint32_t b = sBase + (uint32_t)((kc % 3) * STG_FL) * 4u;
            cpa16(b + (uint32_t)(lq_r*40 + lq_c)*4u,
                  &Q[(size_t)(i0 + lq_r)*DIM + kc*32 + lq_c]);
            #pragma unroll
            for (int p = 0; p < 4; p++) {
                int r = lk_r + p*64;
                cpa16(b + (uint32_t)(2560 + r*40 + lk_c)*4u,
                      &K[(size_t)(j0 + r)*DIM + kc*32 + lk_c]);
            }
            if (tid < 256) {
                int dr = kc*4 + ld_r;
                cpa16(sDs + (uint32_t)(dr*260 + ld_c)*4u,
                      &D[(size_t)(i0 + dr)*NROWS + j0 + ld_c]);
            }
            CPA_COMMIT();
        };

        issue_qk(0);
        issue_qk(1);

        float s[2][4][4];
        #pragma unroll
        for (int f = 0; f < 2; f++)
            #pragma unroll
            for (int g = 0; g < 4; g++)
                #pragma unroll
                for (int e = 0; e < 4; e++) s[f][g][e] = 0.f;

        // ---------------- QK:  S = Q @ K[j0:j0+256]^T ----------------
        #pragma unroll 1
        for (int kc = 0; kc < 16; kc++) {
            if (kc < 15) { CPA_WAIT1(); } else { CPA_WAIT0(); }
            __syncthreads();
            if (kc < 14) issue_qk(kc + 2);
            const float* Qs = ring + (kc % 3) * STG_FL;
            const float* Ks = Qs + 2560;
            #pragma unroll
            for (int k8 = 0; k8 < 4; k8++) {
                const int kp = k8*8 + 2*qc;     // paired (k, k+4)
                float a[2][4];
                #pragma unroll
                for (int f = 0; f < 2; f++) {
                    int rb = wm*32 + f*16 + qr;
                    float2 a0 = *(const float2*)&Qs[rb*40 + kp];
                    float2 a1 = *(const float2*)&Qs[(rb+8)*40 + kp];
                    a[f][0] = a0.x; a[f][1] = a1.x; a[f][2] = a0.y; a[f][3] = a1.y;
                }
                #pragma unroll
                for (int g = 0; g < 4; g++) {
                    int nb = wn*32 + g*8 + qr;
                    float2 bb = *(const float2*)&Ks[nb*40 + kp];
                    float b[2] = { bb.x, bb.y };
                    mma8(s[0][g], a[0], b);
                    mma8(s[1][g], a[1], b);
                }
            }
        }
        __syncthreads();   // QK reads done -> Ssp / vslot0,1 (alias ring) usable

        // ---- SV stage issue (stage st -> vslot st%4, 16 V'' rows, LINEAR) ----
        auto issue_v = [&](int st) {
            uint32_t b = sBase + (uint32_t)vofs[st & 3] * 4u;
            const float* src = V + (size_t)(j0 + st*16) * DIM;
            #pragma unroll
            for (int p = 0; p < 4; p++)
                cpa16(b + (uint32_t)(tid*4 + p*2048)*4u, src + tid*4 + p*2048);
            CPA_COMMIT();
        };

        issue_v(0);
        issue_v(1);

        // ------- D-phase: Ssp = tf32(S .* Ds), pair-interleaved writes -------
        #pragma unroll
        for (int f = 0; f < 2; f++)
            #pragma unroll
            for (int g = 0; g < 4; g++) {
                int r = wm*32 + f*16 + qr;
                int c = wn*32 + g*8 + 2*qc;
                int G8 = (wn*4 + g)*8;
                float2 d0 = *(float2*)&Ds[r][c];
                float2 d1 = *(float2*)&Ds[r+8][c];
                Ssp[r*264 + G8 + spos]         = tf32r(s[f][g][0]*d0.x);
                Ssp[r*264 + G8 + spos + 2]     = tf32r(s[f][g][1]*d0.y);
                Ssp[(r+8)*264 + G8 + spos]     = tf32r(s[f][g][2]*d1.x);
                Ssp[(r+8)*264 + G8 + spos + 2] = tf32r(s[f][g][3]*d1.y);
            }
        __syncthreads();   // Ds reads done -> vslot2,3 (alias Ds) usable

        issue_v(2);

        // ------------- SV:  O += Ssp @ V[j0:j0+256]  (16 stages) -------------
        #pragma unroll 1
        for (int st = 0; st < 16; st++) {
            if (st < 14) { CPA_WAIT2(); }
            else if (st < 15) { CPA_WAIT1(); }
            else { CPA_WAIT0(); }
            __syncthreads();
            if (st + 3 < 16) issue_v(st + 3);
            const float* Vb = sm + vofs[st & 3];
            #pragma unroll
            for (int sub = 0; sub < 2; sub++) {
                const int G8 = (st*2 + sub)*8;
                float a[2][4];
                #pragma unroll
                for (int f = 0; f < 2; f++) {
                    int rb = wm*32 + f*16 + qr;
                    float2 p0 = *(const float2*)&Ssp[rb*264 + G8 + 2*qc];
                    float2 p1 = *(const float2*)&Ssp[(rb+8)*264 + G8 + 2*qc];
                    a[f][0] = p0.x; a[f][1] = p1.x; a[f][2] = p0.y; a[f][3] = p1.y;
                }
                const float* vg = Vb + sub*4096 + 2*qc;
                #pragma unroll
                for (int g = 0; g < 8; g++) {
                    int n = wn*64 + g*8 + qr;
                    float2 bb = *(const float2*)&vg[n*8];   // (V[k][n], V[k+4][n])
                    float b[2] = { bb.x, bb.y };
                    mma8(o[0][g], a[0], b);
                    mma8(o[1][g], a[1], b);
                }
            }
        }
        __syncthreads();   // all Ssp/V reads done before next chunk's issues
    }

    // ---------------- epilogue ----------------
    #pragma unroll
    for (int f = 0; f < 2; f++)
        #pragma unroll
        for (int g = 0; g < 8; g++) {
            int r = i0 + wm*32 + f*16 + qr;
            int c = wn*64 + g*8 + 2*qc;
            *(float2*)&O[(size_t)r*DIM + c]       = make_float2(o[f][g][0], o[f][g][1]);
            *(float2*)&O[(size_t)(r + 8)*DIM + c] = make_float2(o[f][g][2], o[f][g][3]);
        }
}

// ===========================================================================
// Small GEMMs, single-pass tf32: C = act(A @ B + bias).  BM=128, BN=64, BK=32.
// 256 thr, warps 4(m) x 2(n), warp tile 32x32.
// PERM=1: pair-interleave output cols within 8-groups (Q, K).
// PERM=2: V'' layout: (j,n) -> (j>>3)*4096 + n*8 + pp(j&7).
// GN=1:  fused GroupNorm (warp n-range = one 32-channel group).
// ===========================================================================
#define GEMM_SMEM 27648

template<int ACT, int ROUND, int PERM, int GN>
__global__ void __launch_bounds__(256) gemm_tf32(
    const float* __restrict__ A, const float* __restrict__ B,
    const float* __restrict__ bias,
    const float* __restrict__ gamma, const float* __restrict__ beta,
    float* __restrict__ C)
{
    extern __shared__ float sm[];
    float (*As)[36] = (float(*)[36]) sm;
    float (*Bs)[72] = (float(*)[72])(sm + 4608);

    const int tid = threadIdx.x;
    const int lane = tid & 31, w = tid >> 5;
    const int wm = w >> 1, wn = w & 1;
    const int qr = lane >> 2, qc = lane & 3;
    const int bm = blockIdx.x * 128, bn = blockIdx.y * 64;

    float acc[2][4][4];
    #pragma unroll
    for (int f = 0; f < 2; f++)
        #pragma unroll
        for (int g = 0; g < 4; g++)
            #pragma unroll
            for (int e = 0; e < 4; e++) acc[f][g][e] = 0.f;

    float4 ap[4]; float4 bp[2];
    #pragma unroll
    for (int p = 0; p < 4; p++) {
        int idx = tid + p*256, r = idx >> 3, c4 = (idx & 7) * 4;
        ap[p] = *(const float4*)&A[(size_t)(bm + r)*DIM + c4];
    }
    #pragma unroll
    for (int p = 0; p < 2; p++) {
        int idx = tid + p*256, r = idx >> 4, c4 = (idx & 15) * 4;
        bp[p] = *(const float4*)&B[(size_t)r*DIM + bn + c4];
    }

    #pragma unroll 1
    for (int kc = 0; kc < 16; kc++) {
        #pragma unroll
        for (int p = 0; p < 4; p++) {
            int idx = tid + p*256, r = idx >> 3, c4 = (idx & 7) * 4;
            As[r][c4+0] = tf32r(ap[p].x); As[r][c4+1] = tf32r(ap[p].y);
            As[r][c4+2] = tf32r(ap[p].z); As[r][c4+3] = tf32r(ap[p].w);
        }
        #pragma unroll
        for (int p = 0; p < 2; p++) {
            int idx = tid + p*256, r = idx >> 4, c4 = (idx & 15) * 4;
            Bs[r][c4+0] = tf32r(bp[p].x); Bs[r][c4+1] = tf32r(bp[p].y);
            Bs[r][c4+2] = tf32r(bp[p].z); Bs[r][c4+3] = tf32r(bp[p].w);
        }
        __syncthreads();
        if (kc < 15) {
            #pragma unroll
            for (int p = 0; p < 4; p++) {
                int idx = tid + p*256, r = idx >> 3, c4 = (idx & 7) * 4;
                ap[p] = *(const float4*)&A[(size_t)(bm + r)*DIM + (kc+1)*32 + c4];
            }
            #pragma unroll
            for (int p = 0; p < 2; p++) {
                int idx = tid + p*256, r = idx >> 4, c4 = (idx & 15) * 4;
                bp[p] = *(const float4*)&B[(size_t)((kc+1)*32 + r)*DIM + bn + c4];
            }
        }
        #pragma unroll
        for (int k8 = 0; k8 < 4; k8++) {
            const int kk = k8*8 + qc;
            float a[2][4];
            #pragma unroll
            for (int f = 0; f < 2; f++) {
                int rb = wm*32 + f*16 + qr;
                a[f][0] = As[rb][kk];   a[f][1] = As[rb+8][kk];
                a[f][2] = As[rb][kk+4]; a[f][3] = As[rb+8][kk+4];
            }
            #pragma unroll
            for (int g = 0; g < 4; g++) {
                int n = wn*32 + g*8 + qr;
                float b[2] = { Bs[kk][n], Bs[kk+4][n] };
                mma8(acc[0][g], a[0], b);
                mma8(acc[1][g], a[1], b);
            }
        }
        __syncthreads();
    }

    // ------------------------------ epilogue ------------------------------
    #pragma unroll
    for (int f = 0; f < 2; f++)
        #pragma unroll
        for (int g = 0; g < 4; g++) {
            int c = bn + wn*32 + g*8 + 2*qc;
            float2 bb = *(const float2*)&bias[c];
            acc[f][g][0] += bb.x; acc[f][g][1] += bb.y;
            acc[f][g][2] += bb.x; acc[f][g][3] += bb.y;
            if (ACT == 1) {
                #pragma unroll
                for (int e = 0; e < 4; e++) {
                    float v = acc[f][g][e];
                    acc[f][g][e] = 0.5f*v*(1.f + erff(v*0.70710678118654752f));
                }
            }
            if (ROUND == 1) {
                #pragma unroll
                for (int e = 0; e < 4; e++) acc[f][g][e] = tf32r(acc[f][g][e]);
            }
        }

    if (GN == 1) {
        // warp n-range = one 32-channel group; per-row stats via shfl over qc
        #pragma unroll
        for (int f = 0; f < 2; f++) {
            float s0 = 0.f, q0 = 0.f, s1 = 0.f, q1 = 0.f;
            #pragma unroll
            for (int g = 0; g < 4; g++) {
                s0 += acc[f][g][0] + acc[f][g][1];
                q0 += acc[f][g][0]*acc[f][g][0] + acc[f][g][1]*acc[f][g][1];
                s1 += acc[f][g][2] + acc[f][g][3];
                q1 += acc[f][g][2]*acc[f][g][2] + acc[f][g][3]*acc[f][g][3];
            }
            #pragma unroll
            for (int off = 1; off <= 2; off <<= 1) {
                s0 += __shfl_xor_sync(0xffffffff, s0, off);
                q0 += __shfl_xor_sync(0xffffffff, q0, off);
                s1 += __shfl_xor_sync(0xffffffff, s1, off);
                q1 += __shfl_xor_sync(0xffffffff, q1, off);
            }
            float mu0 = s0*(1.f/32.f), iv0 = rsqrtf(q0*(1.f/32.f) - mu0*mu0 + 1e-5f);
            float mu1 = s1*(1.f/32.f), iv1 = rsqrtf(q1*(1.f/32.f) - mu1*mu1 + 1e-5f);
            #pragma unroll
            for (int g = 0; g < 4; g++) {
                int c = bn + wn*32 + g*8 + 2*qc;
                float2 gm = *(const float2*)&gamma[c];
                float2 bt = *(const float2*)&beta[c];
                acc[f][g][0] = (acc[f][g][0] - mu0)*iv0*gm.x + bt.x;
                acc[f][g][1] = (acc[f][g][1] - mu0)*iv0*gm.y + bt.y;
                acc[f][g][2] = (acc[f][g][2] - mu1)*iv1*gm.x + bt.x;
                acc[f][g][3] = (acc[f][g][3] - mu1)*iv1*gm.y + bt.y;
            }
        }
    }

    #pragma unroll
    for (int f = 0; f < 2; f++)
        #pragma unroll
        for (int g = 0; g < 4; g++) {
            int r = bm + wm*32 + f*16 + qr;
            int c = bn + wn*32 + g*8 + 2*qc;
            float v0 = acc[f][g][0], v1 = acc[f][g][1];
            float v2 = acc[f][g][2], v3 = acc[f][g][3];
            if (PERM == 1) {
                int m0 = c & 7, m1 = (c + 1) & 7;
                int p0 = (c & ~7) + ((m0 < 4) ? 2*m0 : 2*(m0-4)+1);
                int p1 = (c & ~7) + ((m1 < 4) ? 2*m1 : 2*(m1-4)+1);
                C[(size_t)r*DIM + p0]       = v0;
                C[(size_t)r*DIM + p1]       = v1;
                C[(size_t)(r + 8)*DIM + p0] = v2;
                C[(size_t)(r + 8)*DIM + p1] = v3;
            } else if (PERM == 2) {
                // V'': (j,n) -> (j>>3)*4096 + n*8 + pp(j&7);  j&7 == qr here
                int ppr = (qr < 4) ? 2*qr : 2*(qr-4)+1;
                size_t a0 = (size_t)(r >> 3)*4096 + (size_t)c*8 + ppr;
                C[a0]          = v0;
                C[a0 + 8]      = v1;
                C[a0 + 4096]   = v2;
                C[a0 + 4104]   = v3;
            } else {
                *(float2*)&C[(size_t)r*DIM + c]       = make_float2(v0, v1);
                *(float2*)&C[(size_t)(r + 8)*DIM + c] = make_float2(v2, v3);
            }
        }
}

// ---------------------------------------------------------------------------
extern "C" void kernel_launch(void* const* d_in, const int* in_sizes, int n_in,
                              void* d_out, int out_size)
{
    const float* x     = (const float*)d_in[0];
    const float* D     = (const float*)d_in[1];
    const float* Wq    = (const float*)d_in[2];
    const float* bq    = (const float*)d_in[3];
    const float* Wk    = (const float*)d_in[4];
    const float* bk    = (const float*)d_in[5];
    const float* Wv    = (const float*)d_in[6];
    const float* bv    = (const float*)d_in[7];
    const float* Wf    = (const float*)d_in[8];
    const float* bf    = (const float*)d_in[9];
    const float* Wp    = (const float*)d_in[10];
    const float* bp    = (const float*)d_in[11];
    const float* gamma = (const float*)d_in[12];
    const float* beta  = (const float*)d_in[13];
    float* out = (float*)d_out;

    float *Q, *K, *V, *XR, *H;
    cudaGetSymbolAddress((void**)&Q,  g_Q);
    cudaGetSymbolAddress((void**)&K,  g_K);
    cudaGetSymbolAddress((void**)&V,  g_V);
    cudaGetSymbolAddress((void**)&XR, g_XR);
    cudaGetSymbolAddress((void**)&H,  g_H);

    cudaFuncSetAttribute(gemm_tf32<0,1,1,0>,
                         cudaFuncAttributeMaxDynamicSharedMemorySize, GEMM_SMEM);
    cudaFuncSetAttribute(gemm_tf32<0,1,2,0>,
                         cudaFuncAttributeMaxDynamicSharedMemorySize, GEMM_SMEM);
    cudaFuncSetAttribute(gemm_tf32<1,0,0,0>,
                         cudaFuncAttributeMaxDynamicSharedMemorySize, GEMM_SMEM);
    cudaFuncSetAttribute(gemm_tf32<0,0,0,1>,
                         cudaFuncAttributeMaxDynamicSharedMemorySize, GEMM_SMEM);
    cudaFuncSetAttribute(retention_mma,
                         cudaFuncAttributeMaxDynamicSharedMemorySize, RET_SMEM);

    dim3 gs(NROWS/128, DIM/64);    // 64 x 8
    gemm_tf32<0,1,1,0><<<gs, 256, GEMM_SMEM>>>(x, Wq, bq, 0, 0, Q);   // Q paired
    gemm_tf32<0,1,1,0><<<gs, 256, GEMM_SMEM>>>(x, Wk, bk, 0, 0, K);   // K paired
    gemm_tf32<0,1,2,0><<<gs, 256, GEMM_SMEM>>>(x, Wv, bv, 0, 0, V);   // V''

    retention_mma<<<NROWS/64, 512, RET_SMEM>>>(Q, K, V, D, XR);

    gemm_tf32<1,0,0,0><<<gs, 256, GEMM_SMEM>>>(XR, Wf, bf, 0, 0, H);  // GELU
    gemm_tf32<0,0,0,1><<<gs, 256, GEMM_SMEM>>>(H, Wp, bp, gamma, beta, out); // +GN
}

// round 15
// speedup vs baseline: 1.2519x; 1.0048x over previous
#include <cuda_runtime.h>
#include <mma.h>
#include <math.h>
#include <stdint.h>

#define NROWS 8192
#define DIM 512

__device__ float g_Q [NROWS*DIM];
__device__ float g_K [NROWS*DIM];
__device__ float g_V [NROWS*DIM];
__device__ float g_XR[NROWS*DIM];
__device__ float g_H [NROWS*DIM];

__device__ __forceinline__ float tf32r(float v) { return nvcuda::wmma::__float_to_tf32(v); }

__device__ __forceinline__ void mma8(float* c, const float* a, const float* b) {
    asm volatile("mma.sync.aligned.m16n8k8.row.col.f32.tf32.tf32.f32 "
        "{%0,%1,%2,%3}, {%4,%5,%6,%7}, {%8,%9}, {%0,%1,%2,%3};"
        : "+f"(c[0]), "+f"(c[1]), "+f"(c[2]), "+f"(c[3])
        : "r"(__float_as_uint(a[0])), "r"(__float_as_uint(a[1])),
          "r"(__float_as_uint(a[2])), "r"(__float_as_uint(a[3])),
          "r"(__float_as_uint(b[0])), "r"(__float_as_uint(b[1])));
}

__device__ __forceinline__ void cpa16(uint32_t dst, const void* src) {
    asm volatile("cp.async.cg.shared.global [%0], [%1], 16;" :: "r"(dst), "l"(src));
}
#define CPA_COMMIT() asm volatile("cp.async.commit_group;" ::: "memory")
#define CPA_WAIT0()  asm volatile("cp.async.wait_group 0;"  ::: "memory")
#define CPA_WAIT1()  asm volatile("cp.async.wait_group 1;"  ::: "memory")
#define CPA_WAIT2()  asm volatile("cp.async.wait_group 2;"  ::: "memory")

// ===========================================================================
// Retention: O = (D .* (Q K^T)) @ V.  Same structure as round 14 (proven):
// CTA = 64 Q-rows, 512 thr, j-chunk 256, QK 3-slot ring w/ folded D loads,
// pair-interleaved Q/K/Ssp, V'' layout, SV 4-slot 16-row stages.
// THIS ROUND: full strength reduction — rolling slot/gmem pointers, hoisted
// per-thread fragment offsets, immediate-offset LDS, no vofs[] array.
// ===========================================================================
#define STG_FL   12800
#define RING_FL  38400
#define REG2_FL  16640
#define SSP_FL   16896              // 64 x 264
#define RET_SMEM ((RING_FL + REG2_FL) * 4)

__global__ void __launch_bounds__(512, 1) retention_mma(
    const float* __restrict__ Q, const float* __restrict__ K,
    const float* __restrict__ V, const float* __restrict__ D,
    float* __restrict__ O)
{
    extern __shared__ float sm[];
    float* Ssp = sm;

    const int tid = threadIdx.x;
    const int lane = tid & 31, w = tid >> 5;
    const int wm = w >> 3, wn = w & 7;       // 2 x 8 warp grid
    const int qr = lane >> 2, qc = lane & 3;
    const int i0 = blockIdx.x * 64;

    const uint32_t sBase = (uint32_t)__cvta_generic_to_shared(sm);
    const uint32_t slotB = (uint32_t)STG_FL * 4u;

    // ---- hoisted loader constants ----
    const int l_r = tid >> 3, l_c = (tid & 7) * 4;        // Q/K loader
    const uint32_t qSm = (uint32_t)(l_r*40 + l_c) * 4u;   // within-slot (Q part)
    const uint32_t kSm = qSm + 2560u*4u;                  // within-slot (K part)
    const int ld_r = tid >> 6, ld_c = (tid & 63) * 4;     // D loader (tid<256)
    const uint32_t dSm0 = sBase + (uint32_t)RING_FL*4u
                        + (uint32_t)(ld_r*260 + ld_c)*4u;
    const uint32_t vSm = (uint32_t)tid * 16u;             // V loader (tid*4 fl)

    const float* Qg = Q + (size_t)(i0 + l_r)*DIM + l_c;

    // ---- hoisted compute constants (float offsets) ----
    const int aQ  = (wm*32 + qr)*40 + 2*qc;               // QK A-frag base
    const int bK  = 2560 + (wn*32 + qr)*40 + 2*qc;        // QK B-frag base
    const int dR  = (wm*32 + qr)*260 + wn*32 + 2*qc;      // Ds read base
    const int spos = ((2*qc) & 3) * 2 + (qc >> 1);
    const int sW  = (wm*32 + qr)*264 + wn*32 + spos;      // Ssp write base
    const int sA  = (wm*32 + qr)*264 + 2*qc;              // Ssp read base (SV A)
    const int vB  = (wn*64 + qr)*8 + 2*qc;                // V'' B-frag base

    float o[2][8][4];
    #pragma unroll
    for (int f = 0; f < 2; f++)
        #pragma unroll
        for (int g = 0; g < 8; g++)
            #pragma unroll
            for (int e = 0; e < 4; e++) o[f][g][e] = 0.f;

    #pragma unroll 1
    for (int j0 = 0; j0 < NROWS; j0 += 256) {
        // -------- QK phase: rolling issue state --------
        const float* qq = Qg;
        const float* kk = K + (size_t)(j0 + l_r)*DIM + l_c;
        const float* dd = D + (size_t)(i0 + ld_r)*NROWS + j0 + ld_c;
        uint32_t bI = sBase;
        uint32_t dI = dSm0;

        auto issue_qk = [&]() {
            cpa16(bI + qSm, qq);
            cpa16(bI + kSm,           kk);
            cpa16(bI + kSm + 10240u,  kk + 64*DIM);
            cpa16(bI + kSm + 20480u,  kk + 128*DIM);
            cpa16(bI + kSm + 30720u,  kk + 192*DIM);
            if (tid < 256) cpa16(dI, dd);
            CPA_COMMIT();
            qq += 32; kk += 32; dd += 4*NROWS; dI += 4160u;
            bI += slotB; if (bI == sBase + 3u*slotB) bI = sBase;
        };

        issue_qk();
        issue_qk();

        float s[2][4][4];
        #pragma unroll
        for (int f = 0; f < 2; f++)
            #pragma unroll
            for (int g = 0; g < 4; g++)
                #pragma unroll
                for (int e = 0; e < 4; e++) s[f][g][e] = 0.f;

        const float* Su = sm;        // rolling use-slot base
        #pragma unroll 1
        for (int kc = 0; kc < 16; kc++) {
            if (kc < 15) { CPA_WAIT1(); } else { CPA_WAIT0(); }
            __syncthreads();
            if (kc < 14) issue_qk();
            const float* Qa = Su + aQ;
            const float* Kb = Su + bK;
            #pragma unroll
            for (int k8 = 0; k8 < 4; k8++) {
                const int kp = k8*8;
                float2 a00 = *(const float2*)(Qa + kp);
                float2 a01 = *(const float2*)(Qa + kp + 320);
                float2 a10 = *(const float2*)(Qa + kp + 640);
                float2 a11 = *(const float2*)(Qa + kp + 960);
                float a0[4] = { a00.x, a01.x, a00.y, a01.y };
                float a1[4] = { a10.x, a11.x, a10.y, a11.y };
                #pragma unroll
                for (int g = 0; g < 4; g++) {
                    float2 bb = *(const float2*)(Kb + kp + g*320);
                    float b[2] = { bb.x, bb.y };
                    mma8(s[0][g], a0, b);
                    mma8(s[1][g], a1, b);
                }
            }
            Su += STG_FL; if (Su == sm + 3*STG_FL) Su = sm;
        }
        __syncthreads();   // QK reads done -> Ssp / vslot0,1 (alias ring) usable

        // -------- SV issue: rolling state, branchless slot address --------
        const float* vv = V + (size_t)j0 * DIM + tid*4;
        int vIss = 0;
        auto issue_v = [&]() {
            int i = vIss & 3;
            uint32_t b = sBase
                + (uint32_t)(((i & 2) ? RING_FL : SSP_FL) + (i & 1)*8192) * 4u
                + vSm;
            cpa16(b,          vv);
            cpa16(b + 8192u,  vv + 2048);
            cpa16(b + 16384u, vv + 4096);
            cpa16(b + 24576u, vv + 6144);
            CPA_COMMIT();
            vv += 8192; vIss++;
        };

        issue_v();
        issue_v();

        // -------- D-phase: Ssp = tf32(S .* Ds), hoisted addressing --------
        {
            const float* DsB = sm + RING_FL + dR;
            float* SspW = Ssp + sW;
            #pragma unroll
            for (int f = 0; f < 2; f++)
                #pragma unroll
                for (int g = 0; g < 4; g++) {
                    float2 d0 = *(const float2*)(DsB + f*4160 + g*8);
                    float2 d1 = *(const float2*)(DsB + f*4160 + g*8 + 2080);
                    float* wp = SspW + f*4224 + g*8;
                    wp[0]    = tf32r(s[f][g][0]*d0.x);
                    wp[2]    = tf32r(s[f][g][1]*d0.y);
                    wp[2112] = tf32r(s[f][g][2]*d1.x);
                    wp[2114] = tf32r(s[f][g][3]*d1.y);
                }
        }
        __syncthreads();   // Ds reads done -> vslot2,3 (alias Ds) usable

        issue_v();

        // -------- SV: O += Ssp @ V''  (16 stages) --------
        const float* SspA = Ssp + sA;
        #pragma unroll 1
        for (int st = 0; st < 16; st++) {
            if (st < 14) { CPA_WAIT2(); }
            else if (st < 15) { CPA_WAIT1(); }
            else { CPA_WAIT0(); }
            __syncthreads();
            if (st + 3 < 16) issue_v();
            const float* Vb = sm
                + (((st & 2) ? RING_FL : SSP_FL) + (st & 1)*8192) + vB;
            #pragma unroll
            for (int sub = 0; sub < 2; sub++) {
                const int G8 = (st*2 + sub)*8;
                float2 p00 = *(const float2*)(SspA + G8);
                float2 p01 = *(const float2*)(SspA + G8 + 2112);
                float2 p10 = *(const float2*)(SspA + G8 + 4224);
                float2 p11 = *(const float2*)(SspA + G8 + 6336);
                float a0[4] = { p00.x, p01.x, p00.y, p01.y };
                float a1[4] = { p10.x, p11.x, p10.y, p11.y };
                const float* vp = Vb + sub*4096;
                #pragma unroll
                for (int g = 0; g < 8; g++) {
                    float2 bb = *(const float2*)(vp + g*64);
                    float b[2] = { bb.x, bb.y };
                    mma8(o[0][g], a0, b);
                    mma8(o[1][g], a1, b);
                }
            }
        }
        __syncthreads();   // all Ssp/V reads done before next chunk's issues
    }

    // ---------------- epilogue ----------------
    #pragma unroll
    for (int f = 0; f < 2; f++)
        #pragma unroll
        for (int g = 0; g < 8; g++) {
            int r = i0 + wm*32 + f*16 + qr;
            int c = wn*64 + g*8 + 2*qc;
            *(float2*)&O[(size_t)r*DIM + c]       = make_float2(o[f][g][0], o[f][g][1]);
            *(float2*)&O[(size_t)(r + 8)*DIM + c] = make_float2(o[f][g][2], o[f][g][3]);
        }
}

// ===========================================================================
// Merged Q/K/V producer GEMM: one launch, grid (64, 24); seg = by>>3 picks
// W/bias/output.  Q,K outputs pair-interleaved (PERM1); V output V'' (PERM2).
// BM=128, BN=64, BK=32, 256 thr, warp tile 32x32, single-pass tf32.
// ===========================================================================
#define GEMM_SMEM 27648

__global__ void __launch_bounds__(256) gemm_qkv(
    const float* __restrict__ A,
    const float* __restrict__ Wq, const float* __restrict__ bq, float* __restrict__ Qo,
    const float* __restrict__ Wk, const float* __restrict__ bk, float* __restrict__ Ko,
    const float* __restrict__ Wv, const float* __restrict__ bv, float* __restrict__ Vo)
{
    extern __shared__ float sm[];
    float (*As)[36] = (float(*)[36]) sm;
    float (*Bs)[72] = (float(*)[72])(sm + 4608);

    const int seg = blockIdx.y >> 3;
    const float* B    = seg == 0 ? Wq : (seg == 1 ? Wk : Wv);
    const float* bias = seg == 0 ? bq : (seg == 1 ? bk : bv);
    float* C          = seg == 0 ? Qo : (seg == 1 ? Ko : Vo);
    const int bn = (blockIdx.y & 7) * 64;
    const int bm = blockIdx.x * 128;

    const int tid = threadIdx.x;
    const int lane = tid & 31, w = tid >> 5;
    const int wm = w >> 1, wn = w & 1;
    const int qr = lane >> 2, qc = lane & 3;

    float acc[2][4][4];
    #pragma unroll
    for (int f = 0; f < 2; f++)
        #pragma unroll
        for (int g = 0; g < 4; g++)
            #pragma unroll
            for (int e = 0; e < 4; e++) acc[f][g][e] = 0.f;

    float4 ap[4]; float4 bp[2];
    #pragma unroll
    for (int p = 0; p < 4; p++) {
        int idx = tid + p*256, r = idx >> 3, c4 = (idx & 7) * 4;
        ap[p] = *(const float4*)&A[(size_t)(bm + r)*DIM + c4];
    }
    #pragma unroll
    for (int p = 0; p < 2; p++) {
        int idx = tid + p*256, r = idx >> 4, c4 = (idx & 15) * 4;
        bp[p] = *(const float4*)&B[(size_t)r*DIM + bn + c4];
    }

    #pragma unroll 1
    for (int kc = 0; kc < 16; kc++) {
        #pragma unroll
        for (int p = 0; p < 4; p++) {
            int idx = tid + p*256, r = idx >> 3, c4 = (idx & 7) * 4;
            As[r][c4+0] = tf32r(ap[p].x); As[r][c4+1] = tf32r(ap[p].y);
            As[r][c4+2] = tf32r(ap[p].z); As[r][c4+3] = tf32r(ap[p].w);
        }
        #pragma unroll
        for (int p = 0; p < 2; p++) {
            int idx = tid + p*256, r = idx >> 4, c4 = (idx & 15) * 4;
            Bs[r][c4+0] = tf32r(bp[p].x); Bs[r][c4+1] = tf32r(bp[p].y);
            Bs[r][c4+2] = tf32r(bp[p].z); Bs[r][c4+3] = tf32r(bp[p].w);
        }
        __syncthreads();
        if (kc < 15) {
            #pragma unroll
            for (int p = 0; p < 4; p++) {
                int idx = tid + p*256, r = idx >> 3, c4 = (idx & 7) * 4;
                ap[p] = *(const float4*)&A[(size_t)(bm + r)*DIM + (kc+1)*32 + c4];
            }
            #pragma unroll
            for (int p = 0; p < 2; p++) {
                int idx = tid + p*256, r = idx >> 4, c4 = (idx & 15) * 4;
                bp[p] = *(const float4*)&B[(size_t)((kc+1)*32 + r)*DIM + bn + c4];
            }
        }
        #pragma unroll
        for (int k8 = 0; k8 < 4; k8++) {
            const int kk = k8*8 + qc;
            float a[2][4];
            #pragma unroll
            for (int f = 0; f < 2; f++) {
                int rb = wm*32 + f*16 + qr;
                a[f][0] = As[rb][kk];   a[f][1] = As[rb+8][kk];
                a[f][2] = As[rb][kk+4]; a[f][3] = As[rb+8][kk+4];
            }
            #pragma unroll
            for (int g = 0; g < 4; g++) {
                int n = wn*32 + g*8 + qr;
                float b[2] = { Bs[kk][n], Bs[kk+4][n] };
                mma8(acc[0][g], a[0], b);
                mma8(acc[1][g], a[1], b);
            }
        }
        __syncthreads();
    }

    #pragma unroll
    for (int f = 0; f < 2; f++)
        #pragma unroll
        for (int g = 0; g < 4; g++) {
            int r = bm + wm*32 + f*16 + qr;
            int c = bn + wn*32 + g*8 + 2*qc;
            float2 bb = *(const float2*)&bias[c];
            float v0 = tf32r(acc[f][g][0] + bb.x);
            float v1 = tf32r(acc[f][g][1] + bb.y);
            float v2 = tf32r(acc[f][g][2] + bb.x);
            float v3 = tf32r(acc[f][g][3] + bb.y);
            if (seg < 2) {
                int m0 = c & 7, m1 = (c + 1) & 7;
                int p0 = (c & ~7) + ((m0 < 4) ? 2*m0 : 2*(m0-4)+1);
                int p1 = (c & ~7) + ((m1 < 4) ? 2*m1 : 2*(m1-4)+1);
                C[(size_t)r*DIM + p0]       = v0;
                C[(size_t)r*DIM + p1]       = v1;
                C[(size_t)(r + 8)*DIM + p0] = v2;
                C[(size_t)(r + 8)*DIM + p1] = v3;
            } else {
                int ppr = (qr < 4) ? 2*qr : 2*(qr-4)+1;
                size_t a0 = (size_t)(r >> 3)*4096 + (size_t)c*8 + ppr;
                C[a0]        = v0;
                C[a0 + 8]    = v1;
                C[a0 + 4096] = v2;
                C[a0 + 4104] = v3;
            }
        }
}

// ===========================================================================
// Consumer GEMMs, single-pass tf32: C = act(A @ B + bias) [+ GroupNorm].
// ACT=1: exact GELU.  GN=1: fused GroupNorm (warp n-range = one group).
// ===========================================================================
template<int ACT, int GN>
__global__ void __launch_bounds__(256) gemm_tf32(
    const float* __restrict__ A, const float* __restrict__ B,
    const float* __restrict__ bias,
    const float* __restrict__ gamma, const float* __restrict__ beta,
    float* __restrict__ C)
{
    extern __shared__ float sm[];
    float (*As)[36] = (float(*)[36]) sm;
    float (*Bs)[72] = (float(*)[72])(sm + 4608);

    const int tid = threadIdx.x;
    const int lane = tid & 31, w = tid >> 5;
    const int wm = w >> 1, wn = w & 1;
    const int qr = lane >> 2, qc = lane & 3;
    const int bm = blockIdx.x * 128, bn = blockIdx.y * 64;

    float acc[2][4][4];
    #pragma unroll
    for (int f = 0; f < 2; f++)
        #pragma unroll
        for (int g = 0; g < 4; g++)
            #pragma unroll
            for (int e = 0; e < 4; e++) acc[f][g][e] = 0.f;

    float4 ap[4]; float4 bp[2];
    #pragma unroll
    for (int p = 0; p < 4; p++) {
        int idx = tid + p*256, r = idx >> 3, c4 = (idx & 7) * 4;
        ap[p] = *(const float4*)&A[(size_t)(bm + r)*DIM + c4];
    }
    #pragma unroll
    for (int p = 0; p < 2; p++) {
        int idx = tid + p*256, r = idx >> 4, c4 = (idx & 15) * 4;
        bp[p] = *(const float4*)&B[(size_t)r*DIM + bn + c4];
    }

    #pragma unroll 1
    for (int kc = 0; kc < 16; kc++) {
        #pragma unroll
        for (int p = 0; p < 4; p++) {
            int idx = tid + p*256, r = idx >> 3, c4 = (idx & 7) * 4;
            As[r][c4+0] = tf32r(ap[p].x); As[r][c4+1] = tf32r(ap[p].y);
            As[r][c4+2] = tf32r(ap[p].z); As[r][c4+3] = tf32r(ap[p].w);
        }
        #pragma unroll
        for (int p = 0; p < 2; p++) {
            int idx = tid + p*256, r = idx >> 4, c4 = (idx & 15) * 4;
            Bs[r][c4+0] = tf32r(bp[p].x); Bs[r][c4+1] = tf32r(bp[p].y);
            Bs[r][c4+2] = tf32r(bp[p].z); Bs[r][c4+3] = tf32r(bp[p].w);
        }
        __syncthreads();
        if (kc < 15) {
            #pragma unroll
            for (int p = 0; p < 4; p++) {
                int idx = tid + p*256, r = idx >> 3, c4 = (idx & 7) * 4;
                ap[p] = *(const float4*)&A[(size_t)(bm + r)*DIM + (kc+1)*32 + c4];
            }
            #pragma unroll
            for (int p = 0; p < 2; p++) {
                int idx = tid + p*256, r = idx >> 4, c4 = (idx & 15) * 4;
                bp[p] = *(const float4*)&B[(size_t)((kc+1)*32 + r)*DIM + bn + c4];
            }
        }
        #pragma unroll
        for (int k8 = 0; k8 < 4; k8++) {
            const int kk = k8*8 + qc;
            float a[2][4];
            #pragma unroll
            for (int f = 0; f < 2; f++) {
                int rb = wm*32 + f*16 + qr;
                a[f][0] = As[rb][kk];   a[f][1] = As[rb+8][kk];
                a[f][2] = As[rb][kk+4]; a[f][3] = As[rb+8][kk+4];
            }
            #pragma unroll
            for (int g = 0; g < 4; g++) {
                int n = wn*32 + g*8 + qr;
                float b[2] = { Bs[kk][n], Bs[kk+4][n] };
                mma8(acc[0][g], a[0], b);
                mma8(acc[1][g], a[1], b);
            }
        }
        __syncthreads();
    }

    // epilogue
    #pragma unroll
    for (int f = 0; f < 2; f++)
        #pragma unroll
        for (int g = 0; g < 4; g++) {
            int c = bn + wn*32 + g*8 + 2*qc;
            float2 bb = *(const float2*)&bias[c];
            acc[f][g][0] += bb.x; acc[f][g][1] += bb.y;
            acc[f][g][2] += bb.x; acc[f][g][3] += bb.y;
            if (ACT == 1) {
                #pragma unroll
                for (int e = 0; e < 4; e++) {
                    float v = acc[f][g][e];
                    acc[f][g][e] = 0.5f*v*(1.f + erff(v*0.70710678118654752f));
                }
            }
        }

    if (GN == 1) {
        #pragma unroll
        for (int f = 0; f < 2; f++) {
            float s0 = 0.f, q0 = 0.f, s1 = 0.f, q1 = 0.f;
            #pragma unroll
            for (int g = 0; g < 4; g++) {
                s0 += acc[f][g][0] + acc[f][g][1];
                q0 += acc[f][g][0]*acc[f][g][0] + acc[f][g][1]*acc[f][g][1];
                s1 += acc[f][g][2] + acc[f][g][3];
                q1 += acc[f][g][2]*acc[f][g][2] + acc[f][g][3]*acc[f][g][3];
            }
            #pragma unroll
            for (int off = 1; off <= 2; off <<= 1) {
                s0 += __shfl_xor_sync(0xffffffff, s0, off);
                q0 += __shfl_xor_sync(0xffffffff, q0, off);
                s1 += __shfl_xor_sync(0xffffffff, s1, off);
                q1 += __shfl_xor_sync(0xffffffff, q1, off);
            }
            float mu0 = s0*(1.f/32.f), iv0 = rsqrtf(q0*(1.f/32.f) - mu0*mu0 + 1e-5f);
            float mu1 = s1*(1.f/32.f), iv1 = rsqrtf(q1*(1.f/32.f) - mu1*mu1 + 1e-5f);
            #pragma unroll
            for (int g = 0; g < 4; g++) {
                int c = bn + wn*32 + g*8 + 2*qc;
                float2 gm = *(const float2*)&gamma[c];
                float2 bt = *(const float2*)&beta[c];
                acc[f][g][0] = (acc[f][g][0] - mu0)*iv0*gm.x + bt.x;
                acc[f][g][1] = (acc[f][g][1] - mu0)*iv0*gm.y + bt.y;
                acc[f][g][2] = (acc[f][g][2] - mu1)*iv1*gm.x + bt.x;
                acc[f][g][3] = (acc[f][g][3] - mu1)*iv1*gm.y + bt.y;
            }
        }
    }

    #pragma unroll
    for (int f = 0; f < 2; f++)
        #pragma unroll
        for (int g = 0; g < 4; g++) {
            int r = bm + wm*32 + f*16 + qr;
            int c = bn + wn*32 + g*8 + 2*qc;
            *(float2*)&C[(size_t)r*DIM + c] =
                make_float2(acc[f][g][0], acc[f][g][1]);
            *(float2*)&C[(size_t)(r + 8)*DIM + c] =
                make_float2(acc[f][g][2], acc[f][g][3]);
        }
}

// ---------------------------------------------------------------------------
extern "C" void kernel_launch(void* const* d_in, const int* in_sizes, int n_in,
                              void* d_out, int out_size)
{
    const float* x     = (const float*)d_in[0];
    const float* D     = (const float*)d_in[1];
    const float* Wq    = (const float*)d_in[2];
    const float* bq    = (const float*)d_in[3];
    const float* Wk    = (const float*)d_in[4];
    const float* bk    = (const float*)d_in[5];
    const float* Wv    = (const float*)d_in[6];
    const float* bv    = (const float*)d_in[7];
    const float* Wf    = (const float*)d_in[8];
    const float* bf    = (const float*)d_in[9];
    const float* Wp    = (const float*)d_in[10];
    const float* bp    = (const float*)d_in[11];
    const float* gamma = (const float*)d_in[12];
    const float* beta  = (const float*)d_in[13];
    float* out = (float*)d_out;

    float *Q, *K, *V, *XR, *H;
    cudaGetSymbolAddress((void**)&Q,  g_Q);
    cudaGetSymbolAddress((void**)&K,  g_K);
    cudaGetSymbolAddress((void**)&V,  g_V);
    cudaGetSymbolAddress((void**)&XR, g_XR);
    cudaGetSymbolAddress((void**)&H,  g_H);

    cudaFuncSetAttribute(gemm_qkv,
                         cudaFuncAttributeMaxDynamicSharedMemorySize, GEMM_SMEM);
    cudaFuncSetAttribute(gemm_tf32<1,0>,
                         cudaFuncAttributeMaxDynamicSharedMemorySize, GEMM_SMEM);
    cudaFuncSetAttribute(gemm_tf32<0,1>,
                         cudaFuncAttributeMaxDynamicSharedMemorySize, GEMM_SMEM);
    cudaFuncSetAttribute(retention_mma,
                         cudaFuncAttributeMaxDynamicSharedMemorySize, RET_SMEM);

    gemm_qkv<<<dim3(NROWS/128, 24), 256, GEMM_SMEM>>>(
        x, Wq, bq, Q, Wk, bk, K, Wv, bv, V);

    retention_mma<<<NROWS/64, 512, RET_SMEM>>>(Q, K, V, D, XR);

    dim3 gs(NROWS/128, DIM/64);
    gemm_tf32<1,0><<<gs, 256, GEMM_SMEM>>>(XR, Wf, bf, 0, 0, H);        // GELU
    gemm_tf32<0,1><<<gs, 256, GEMM_SMEM>>>(H, Wp, bp, gamma, beta, out); // +GN
}